// round 15
// baseline (speedup 1.0000x reference)
#include <cuda_runtime.h>
#include <cuda_fp16.h>
#include <cstdint>
#include <cstddef>

// ---------------- problem constants ----------------
#define BATCH   4
#define SEQ     2048
#define DIM     768
#define HEADS   12
#define HEAD_D  64
#define HIDDEN  3072
#define MTOK    (BATCH * SEQ)        // 8192 tokens
#define QKV_N   (3 * DIM)            // 2304
#define SCALE_ATT 0.125f             // 64^-0.5
#define LN_EPS  1e-5f

// ---------------- scratch (alloc-free: __device__ globals) ----------------
__device__ float g_x1 [(size_t)MTOK * DIM];       // residual after attn branch

__device__ __align__(16) __half g_qkv[(size_t)MTOK * QKV_N]; // q/k/v fp16
__device__ __align__(16) __half g_h  [(size_t)MTOK * DIM];   // LN out fp16
__device__ __align__(16) __half g_at [(size_t)MTOK * DIM];   // attention out fp16
__device__ __align__(16) __half g_u  [(size_t)MTOK * HIDDEN];// FC1/gelu out fp16

// transposed weights: stored [N, K] fp16
__device__ __align__(16) __half g_wqkv[(size_t)QKV_N * DIM];
__device__ __align__(16) __half g_wprj[(size_t)DIM * DIM];
__device__ __align__(16) __half g_wfc1[(size_t)HIDDEN * DIM];
__device__ __align__(16) __half g_wfc2[(size_t)DIM * HIDDEN];

// =====================================================================
// PTX helpers (sm_80-class: mma.sync / ldmatrix / cp.async — OK on sm_103)
// =====================================================================
__device__ __forceinline__ uint32_t smem_u32(const void* p) {
    uint32_t a;
    asm("{ .reg .u64 t; cvta.to.shared.u64 t, %1; cvt.u32.u64 %0, t; }"
        : "=r"(a) : "l"(p));
    return a;
}

#define LDSM_X4(r, addr)                                                        \
    asm volatile("ldmatrix.sync.aligned.m8n8.x4.shared.b16 {%0,%1,%2,%3}, [%4];"\
        : "=r"((r)[0]), "=r"((r)[1]), "=r"((r)[2]), "=r"((r)[3]) : "r"(addr))

#define LDSM_X4_T(r, addr)                                                      \
    asm volatile("ldmatrix.sync.aligned.m8n8.x4.trans.shared.b16 {%0,%1,%2,%3}, [%4];"\
        : "=r"((r)[0]), "=r"((r)[1]), "=r"((r)[2]), "=r"((r)[3]) : "r"(addr))

#define MMA_F16(d, a, b0, b1)                                                   \
    asm volatile("mma.sync.aligned.m16n8k16.row.col.f32.f16.f16.f32 "           \
        "{%0,%1,%2,%3}, {%4,%5,%6,%7}, {%8,%9}, {%0,%1,%2,%3};"                 \
        : "+f"((d)[0]), "+f"((d)[1]), "+f"((d)[2]), "+f"((d)[3])                \
        : "r"((a)[0]), "r"((a)[1]), "r"((a)[2]), "r"((a)[3]), "r"(b0), "r"(b1))

__device__ __forceinline__ void cp16(uint32_t dst, const void* src) {
    asm volatile("cp.async.cg.shared.global [%0], [%1], 16;"
                 :: "r"(dst), "l"(src) : "memory");
}
#define CP_COMMIT() asm volatile("cp.async.commit_group;" ::: "memory")
#define CP_WAIT1()  asm volatile("cp.async.wait_group 1;" ::: "memory")
#define CP_WAIT0()  asm volatile("cp.async.wait_group 0;" ::: "memory")

__device__ __forceinline__ uint32_t pack_f16(float x, float y) {
    __half2 t = __halves2half2(__float2half_rn(x), __float2half_rn(y));
    return *(uint32_t*)&t;
}

__device__ __forceinline__ void store_h2(__half* p, float a, float b) {
    __half2 t = __halves2half2(__float2half_rn(a), __float2half_rn(b));
    *(__half2*)p = t;
}

// =====================================================================
// Combined weight convert: all four W[K,N] fp32 -> Wt[N,K] fp16
// =====================================================================
#define WCONV_BLOCKS 6912

__global__ __launch_bounds__(256) void wconv_all_kernel(
    const float* __restrict__ qkv_w, __half* __restrict__ wq,
    const float* __restrict__ proj_w, __half* __restrict__ wp,
    const float* __restrict__ fc1_w, __half* __restrict__ w1,
    const float* __restrict__ fc2_w, __half* __restrict__ w2)
{
    int bid = blockIdx.x;
    const float* W; __half* T; int K, N, nx;
    if (bid < 1728)      { W = qkv_w;  T = wq; K = DIM;    N = QKV_N;  nx = 72; }
    else if (bid < 2304) { bid -= 1728; W = proj_w; T = wp; K = DIM;   N = DIM;    nx = 24; }
    else if (bid < 4608) { bid -= 2304; W = fc1_w;  T = w1; K = DIM;   N = HIDDEN; nx = 96; }
    else                 { bid -= 4608; W = fc2_w;  T = w2; K = HIDDEN; N = DIM;   nx = 24; }
    const int n0 = (bid % nx) * 32, k0 = (bid / nx) * 32;

    __shared__ float t[32][33];
    const int tx = threadIdx.x, ty = threadIdx.y;
    #pragma unroll
    for (int j = 0; j < 4; j++)
        t[ty + 8 * j][tx] = W[(size_t)(k0 + ty + 8 * j) * N + n0 + tx];
    __syncthreads();
    #pragma unroll
    for (int j = 0; j < 4; j++)
        T[(size_t)(n0 + ty + 8 * j) * K + k0 + tx] = __float2half_rn(t[tx][ty + 8 * j]);
}

// =====================================================================
// LayerNorm -> fp16
// =====================================================================
__global__ __launch_bounds__(256) void ln_kernel(
    const float* __restrict__ x, const float* __restrict__ gamma,
    const float* __restrict__ beta, __half* __restrict__ out)
{
    const int row = blockIdx.x;
    const int tid = threadIdx.x;
    const float* xr = x + (size_t)row * DIM;

    float v0 = xr[tid], v1 = xr[tid + 256], v2 = xr[tid + 512];
    float s = v0 + v1 + v2;
    float q = v0 * v0 + v1 * v1 + v2 * v2;

    __shared__ float ws[8], wq[8];
    #pragma unroll
    for (int o = 16; o; o >>= 1) {
        s += __shfl_xor_sync(0xffffffffu, s, o);
        q += __shfl_xor_sync(0xffffffffu, q, o);
    }
    if ((tid & 31) == 0) { ws[tid >> 5] = s; wq[tid >> 5] = q; }
    __syncthreads();
    float ts = 0.f, tq = 0.f;
    #pragma unroll
    for (int i = 0; i < 8; i++) { ts += ws[i]; tq += wq[i]; }

    const float mean = ts * (1.0f / DIM);
    const float var  = tq * (1.0f / DIM) - mean * mean;
    const float rstd = rsqrtf(var + LN_EPS);

    const size_t rb = (size_t)row * DIM;
    #pragma unroll
    for (int j = 0; j < 3; j++) {
        const int c = tid + j * 256;
        const float v = (j == 0 ? v0 : (j == 1 ? v1 : v2));
        out[rb + c] = __float2half_rn((v - mean) * rstd * gamma[c] + beta[c]);
    }
}

// =====================================================================
// fp16 tensor-core GEMM via mma.sync.m16n8k16 (unchanged from R14)
// =====================================================================
#define GEMM_SMEM(NJ) (3 * (16384 + 4096 * (NJ)))

template<int MODE, int NJ>
__global__ __launch_bounds__(256, 2) void tc_gemm(
    const __half* __restrict__ A, const __half* __restrict__ B,
    const float* __restrict__ bias, const float* __restrict__ res,
    float* __restrict__ outf, __half* __restrict__ out16,
    int N, int K,
    const float* __restrict__ pga, const float* __restrict__ pgb,
    const float* __restrict__ pgc)
{
    constexpr int BN = 32 * NJ;
    constexpr int STAGE = 16384 + 4096 * NJ;
    extern __shared__ char sm[];
    const uint32_t sbase = smem_u32(sm);
    const int tid = threadIdx.x;
    const int lane = tid & 31, wid = tid >> 5;
    const int wm = wid & 3, wn = wid >> 2;
    const int m0 = blockIdx.y * 128, n0 = blockIdx.x * BN;
    const int nt = K >> 6;

    const __half* agsrc[4]; uint32_t asoff[4];
    #pragma unroll
    for (int i = 0; i < 4; i++) {
        const int id = tid + i * 256;
        const int row = id >> 3, c = id & 7;
        agsrc[i] = A + (size_t)(m0 + row) * K + c * 8;
        asoff[i] = row * 128 + ((c ^ (row & 7)) << 4);
    }
    const __half* bgsrc[NJ]; uint32_t bsoff[NJ];
    #pragma unroll
    for (int i = 0; i < NJ; i++) {
        const int id = tid + i * 256;
        const int row = id >> 3, c = id & 7;
        bgsrc[i] = B + (size_t)(n0 + row) * K + c * 8;
        bsoff[i] = 16384 + row * 128 + ((c ^ (row & 7)) << 4);
    }

    #define LOAD_STAGE(kt, slot) do {                                          \
        const uint32_t sb_ = sbase + (uint32_t)(slot) * STAGE;                  \
        const size_t ko_ = (size_t)(kt) * 64;                                   \
        _Pragma("unroll")                                                       \
        for (int i_ = 0; i_ < 4; i_++)                                          \
            cp16(sb_ + asoff[i_], agsrc[i_] + ko_);                             \
        _Pragma("unroll")                                                       \
        for (int i_ = 0; i_ < NJ; i_++)                                         \
            cp16(sb_ + bsoff[i_], bgsrc[i_] + ko_);                             \
    } while (0)

    LOAD_STAGE(0, 0); CP_COMMIT();
    LOAD_STAGE(1, 1); CP_COMMIT();

    uint32_t a_off[2][4];
    #pragma unroll
    for (int mi = 0; mi < 2; mi++) {
        const int row = wm * 32 + mi * 16 + (lane & 15);
        const int kbit = (lane >> 4) & 1;
        #pragma unroll
        for (int ks = 0; ks < 4; ks++) {
            const int chi = ks * 2 + kbit;
            a_off[mi][ks] = row * 128 + ((chi ^ (row & 7)) << 4);
        }
    }
    uint32_t b_off[NJ][4];
    #pragma unroll
    for (int nj = 0; nj < NJ; nj++) {
        const int nrow = wn * (16 * NJ) + nj * 16 + (lane & 7) + ((lane >> 4) << 3);
        const int kbit = (lane >> 3) & 1;
        #pragma unroll
        for (int ks = 0; ks < 4; ks++) {
            const int chi = ks * 2 + kbit;
            b_off[nj][ks] = 16384 + nrow * 128 + ((chi ^ (nrow & 7)) << 4);
        }
    }

    float acc[2][2 * NJ][4] = {};

    for (int kt = 0; kt < nt; kt++) {
        CP_WAIT1();
        __syncthreads();
        const uint32_t sb = sbase + (uint32_t)(kt % 3) * STAGE;

        #pragma unroll
        for (int ks = 0; ks < 4; ks++) {
            uint32_t ar[2][4];
            LDSM_X4(ar[0], sb + a_off[0][ks]);
            LDSM_X4(ar[1], sb + a_off[1][ks]);
            #pragma unroll
            for (int nj = 0; nj < NJ; nj++) {
                uint32_t br[4];
                LDSM_X4(br, sb + b_off[nj][ks]);
                #pragma unroll
                for (int mi = 0; mi < 2; mi++) {
                    MMA_F16(acc[mi][nj * 2    ], ar[mi], br[0], br[1]);
                    MMA_F16(acc[mi][nj * 2 + 1], ar[mi], br[2], br[3]);
                }
            }
        }
        if (kt + 2 < nt) LOAD_STAGE(kt + 2, (kt + 2) % 3);
        CP_COMMIT();
    }

    float gaV = 0.f, gbV = 0.f, gcV = 0.f;
    if (MODE == 2) { gaV = *pga; gbV = *pgb; gcV = *pgc; }

    #pragma unroll
    for (int mi = 0; mi < 2; mi++) {
        const int ma = m0 + wm * 32 + mi * 16 + (lane >> 2);
        #pragma unroll
        for (int t = 0; t < 2 * NJ; t++) {
            const int n = n0 + wn * (16 * NJ) + t * 8 + ((lane & 3) << 1);
            const float b0 = bias[n], b1 = bias[n + 1];
            #pragma unroll
            for (int half = 0; half < 2; half++) {
                const int m = ma + half * 8;
                float v0 = acc[mi][t][half * 2]     + b0;
                float v1 = acc[mi][t][half * 2 + 1] + b1;
                const size_t idx = (size_t)m * N + n;
                if (MODE == 2) {
                    v0 = fmaf(fmaf(gaV, v0, gbV), v0, gcV);
                    v1 = fmaf(fmaf(gaV, v1, gbV), v1, gcV);
                    store_h2(out16 + idx, v0, v1);
                } else if (MODE == 3) {
                    store_h2(out16 + idx, v0, v1);
                } else {
                    const float2 rv = *(const float2*)(res + idx);
                    *(float2*)(outf + idx) = make_float2(v0 + rv.x, v1 + rv.y);
                }
            }
        }
    }
    #undef LOAD_STAGE
}

// =====================================================================
// Tensor-core fused attention, fat-warp version:
// 128 threads (4 warps), each warp owns 32 queries (2 mi blocks of 16).
// K/V fragments are reused across both mi blocks -> smem read traffic
// per CTA halves vs the 8-warp layout (L1 was the binding pipe: 57.8%).
// __launch_bounds__(128, 2): 2 CTAs/SM (<=256 regs/thread budget).
// =====================================================================
__global__ __launch_bounds__(128, 2) void attn_tc_kernel(
    const __half* __restrict__ qkv, __half* __restrict__ out,
    const float* __restrict__ pa_, const float* __restrict__ pb_,
    const float* __restrict__ pc_)
{
    __shared__ __align__(16) char smQ[16384];      // 128 rows x 128B
    __shared__ __align__(16) char smK[2][8192];    // 64 rows x 128B
    __shared__ __align__(16) char smV[2][8192];

    const int tid = threadIdx.x, lane = tid & 31, warp = tid >> 5;
    const int bh = blockIdx.y, b = bh / HEADS, h = bh % HEADS;
    const int q0 = blockIdx.x * 128;
    const size_t tok0 = (size_t)b * SEQ;

    const uint32_t sQ = smem_u32(smQ);
    const uint32_t sK[2] = { smem_u32(smK[0]), smem_u32(smK[1]) };
    const uint32_t sV[2] = { smem_u32(smV[0]), smem_u32(smV[1]) };

    const float pa2 = *pa_ * (SCALE_ATT * SCALE_ATT);
    const float pb2 = *pb_ * SCALE_ATT;
    const float pc  = *pc_;

    // Q loads: 128 rows x 8 chunks / 128 thr = 8 per thread (row = tid)
    {
        const __half* qsrc = qkv + (tok0 + q0 + tid) * QKV_N + h * HEAD_D;
        const uint32_t qb = sQ + tid * 128;
        #pragma unroll
        for (int j = 0; j < 8; j++)
            cp16(qb + ((j ^ (tid & 7)) << 4), qsrc + j * 8);
    }

    // K/V loads: 64 rows x 8 chunks / 128 thr = 4 each
    const int krow = tid >> 1;
    const int kc0  = (tid & 1) * 4;
    const __half* ksrc = qkv + (tok0 + krow) * QKV_N + DIM + h * HEAD_D + kc0 * 8;
    const __half* vsrc = ksrc + DIM;
    uint32_t kvoff[4];
    #pragma unroll
    for (int j = 0; j < 4; j++)
        kvoff[j] = krow * 128 + (((kc0 + j) ^ (krow & 7)) << 4);

    #pragma unroll
    for (int j = 0; j < 4; j++) {
        cp16(sK[0] + kvoff[j], ksrc + j * 8);
        cp16(sV[0] + kvoff[j], vsrc + j * 8);
    }
    CP_COMMIT();
    CP_WAIT0();
    __syncthreads();

    // ---- hoist Q fragments for both mi blocks ----
    const int g = lane >> 3, r = lane & 7;
    const int rowadd = (g & 1) * 8 + r;
    const int cadd = g >> 1;
    uint32_t qreg[2][4][4];
    #pragma unroll
    for (int mi = 0; mi < 2; mi++) {
        const uint32_t qb = sQ + (warp * 32 + mi * 16 + rowadd) * 128;
        #pragma unroll
        for (int s = 0; s < 4; s++)
            LDSM_X4(qreg[mi][s], qb + (((2 * s + cadd) ^ r) << 4));
    }

    float acc_o[2][8][4] = {};
    float rsum[2][2] = {};
    const int NT = SEQ / 64;

    for (int t = 0; t < NT; t++) {
        if (t + 1 < NT) {
            const int nb = (t + 1) & 1;
            const size_t roff = (size_t)(t + 1) * 64 * QKV_N;
            #pragma unroll
            for (int j = 0; j < 4; j++) {
                cp16(sK[nb] + kvoff[j], ksrc + roff + j * 8);
                cp16(sV[nb] + kvoff[j], vsrc + roff + j * 8);
            }
            CP_COMMIT();
            CP_WAIT1();
        } else {
            CP_WAIT0();
        }
        __syncthreads();

        const uint32_t sk = sK[t & 1], sv = sV[t & 1];

        // ---- S = Q K^T : K fragment reused across 2 mi blocks ----
        float acc_s[2][8][4] = {};
        #pragma unroll
        for (int s = 0; s < 4; s++) {
            const uint32_t coff = ((2 * s + cadd) ^ r) << 4;
            #pragma unroll
            for (int p = 0; p < 4; p++) {
                uint32_t kb[4];
                LDSM_X4(kb, sk + (16 * p + rowadd) * 128 + coff);
                #pragma unroll
                for (int mi = 0; mi < 2; mi++) {
                    MMA_F16(acc_s[mi][2 * p    ], qreg[mi][s], kb[0], kb[2]);
                    MMA_F16(acc_s[mi][2 * p + 1], qreg[mi][s], kb[1], kb[3]);
                }
            }
        }

        // ---- poly activation + clamp + rowsum ----
        #pragma unroll
        for (int mi = 0; mi < 2; mi++)
            #pragma unroll
            for (int j = 0; j < 8; j++)
                #pragma unroll
                for (int e = 0; e < 4; e++) {
                    const float sv_ = acc_s[mi][j][e];
                    float pv = fmaf(fmaf(pa2, sv_, pb2), sv_, pc);
                    pv = fmaxf(pv, 1e-6f);
                    acc_s[mi][j][e] = pv;
                    rsum[mi][e >> 1] += pv;
                }

        // ---- O += P V : V fragment reused across 2 mi blocks ----
        #pragma unroll
        for (int s = 0; s < 4; s++) {
            uint32_t pf[2][4];
            #pragma unroll
            for (int mi = 0; mi < 2; mi++) {
                pf[mi][0] = pack_f16(acc_s[mi][2 * s][0],     acc_s[mi][2 * s][1]);
                pf[mi][1] = pack_f16(acc_s[mi][2 * s][2],     acc_s[mi][2 * s][3]);
                pf[mi][2] = pack_f16(acc_s[mi][2 * s + 1][0], acc_s[mi][2 * s + 1][1]);
                pf[mi][3] = pack_f16(acc_s[mi][2 * s + 1][2], acc_s[mi][2 * s + 1][3]);
            }
            const uint32_t vrb = sv + (16 * s + rowadd) * 128;
            #pragma unroll
            for (int p = 0; p < 4; p++) {
                uint32_t vb[4];
                LDSM_X4_T(vb, vrb + (((2 * p + cadd) ^ r) << 4));
                #pragma unroll
                for (int mi = 0; mi < 2; mi++) {
                    MMA_F16(acc_o[mi][2 * p    ], pf[mi], vb[0], vb[1]);
                    MMA_F16(acc_o[mi][2 * p + 1], pf[mi], vb[2], vb[3]);
                }
            }
        }
        __syncthreads();
    }

    // ---- normalize + write ----
    #pragma unroll
    for (int mi = 0; mi < 2; mi++) {
        float r0 = rsum[mi][0], r1 = rsum[mi][1];
        #pragma unroll
        for (int off = 1; off < 4; off <<= 1) {
            r0 += __shfl_xor_sync(0xffffffffu, r0, off);
            r1 += __shfl_xor_sync(0xffffffffu, r1, off);
        }
        const float inv0 = 1.0f / (r0 + 1e-8f);
        const float inv1 = 1.0f / (r1 + 1e-8f);

        const int row0 = q0 + warp * 32 + mi * 16 + (lane >> 2);
        const int dcol = h * HEAD_D + 2 * (lane & 3);
        #pragma unroll
        for (int j = 0; j < 8; j++) {
            const size_t i0 = (tok0 + row0) * DIM + dcol + 8 * j;
            const size_t i1 = (tok0 + row0 + 8) * DIM + dcol + 8 * j;
            store_h2(out + i0, acc_o[mi][j][0] * inv0, acc_o[mi][j][1] * inv0);
            store_h2(out + i1, acc_o[mi][j][2] * inv1, acc_o[mi][j][3] * inv1);
        }
    }
}

// =====================================================================
// Launch
// =====================================================================
extern "C" void kernel_launch(void* const* d_in, const int* in_sizes, int n_in,
                              void* d_out, int out_size)
{
    const float* x      = (const float*)d_in[0];
    const float* ln1_g  = (const float*)d_in[1];
    const float* ln1_b  = (const float*)d_in[2];
    const float* ln2_g  = (const float*)d_in[3];
    const float* ln2_b  = (const float*)d_in[4];
    const float* qkv_w  = (const float*)d_in[5];
    const float* qkv_b  = (const float*)d_in[6];
    const float* proj_w = (const float*)d_in[7];
    const float* proj_b = (const float*)d_in[8];
    const float* fc1_w  = (const float*)d_in[9];
    const float* fc1_b  = (const float*)d_in[10];
    const float* fc2_w  = (const float*)d_in[11];
    const float* fc2_b  = (const float*)d_in[12];
    const float* attn_a = (const float*)d_in[13];
    const float* attn_b = (const float*)d_in[14];
    const float* attn_c = (const float*)d_in[15];
    const float* gelu_a = (const float*)d_in[16];
    const float* gelu_b = (const float*)d_in[17];
    const float* gelu_c = (const float*)d_in[18];

    float *x1;
    __half *qkvh, *hbuf, *atbuf, *ubuf, *wq, *wp, *w1, *w2;
    cudaGetSymbolAddress((void**)&x1,    g_x1);
    cudaGetSymbolAddress((void**)&qkvh,  g_qkv);
    cudaGetSymbolAddress((void**)&hbuf,  g_h);
    cudaGetSymbolAddress((void**)&atbuf, g_at);
    cudaGetSymbolAddress((void**)&ubuf,  g_u);
    cudaGetSymbolAddress((void**)&wq,    g_wqkv);
    cudaGetSymbolAddress((void**)&wp,    g_wprj);
    cudaGetSymbolAddress((void**)&w1,    g_wfc1);
    cudaGetSymbolAddress((void**)&w2,    g_wfc2);

    cudaFuncSetAttribute(tc_gemm<1, 2>, cudaFuncAttributeMaxDynamicSharedMemorySize,
                         GEMM_SMEM(2));
    cudaFuncSetAttribute(tc_gemm<2, 4>, cudaFuncAttributeMaxDynamicSharedMemorySize,
                         GEMM_SMEM(4));
    cudaFuncSetAttribute(tc_gemm<3, 4>, cudaFuncAttributeMaxDynamicSharedMemorySize,
                         GEMM_SMEM(4));

    // 0) all weight transposes + fp16 conversion in ONE launch
    wconv_all_kernel<<<WCONV_BLOCKS, dim3(32, 8)>>>(
        qkv_w, wq, proj_w, wp, fc1_w, w1, fc2_w, w2);

    // 1) LN1 -> fp16
    ln_kernel<<<MTOK, 256>>>(x, ln1_g, ln1_b, hbuf);

    // 2) QKV GEMM -> fp16 q/k/v   (128x128 tiles)
    tc_gemm<3, 4><<<dim3(QKV_N / 128, MTOK / 128), 256, GEMM_SMEM(4)>>>(
        hbuf, wq, qkv_b, nullptr, nullptr, qkvh,
        QKV_N, DIM, nullptr, nullptr, nullptr);

    // 3) fat-warp tensor-core attention (128-query tiles, 128 threads)
    attn_tc_kernel<<<dim3(SEQ / 128, BATCH * HEADS), 128>>>(
        qkvh, atbuf, attn_a, attn_b, attn_c);

    // 4) proj GEMM + residual(x) -> x1 (fp32)   (128x64 tiles)
    tc_gemm<1, 2><<<dim3(DIM / 64, MTOK / 128), 256, GEMM_SMEM(2)>>>(
        atbuf, wp, proj_b, x, x1, nullptr,
        DIM, DIM, nullptr, nullptr, nullptr);

    // 5) LN2 -> fp16
    ln_kernel<<<MTOK, 256>>>(x1, ln2_g, ln2_b, hbuf);

    // 6) FC1 + poly-GELU -> u fp16   (128x128 tiles)
    tc_gemm<2, 4><<<dim3(HIDDEN / 128, MTOK / 128), 256, GEMM_SMEM(4)>>>(
        hbuf, w1, fc1_b, nullptr, nullptr, ubuf,
        HIDDEN, DIM, gelu_a, gelu_b, gelu_c);

    // 7) FC2 + residual(x1) -> out (fp32)   (128x64 tiles)
    tc_gemm<1, 2><<<dim3(DIM / 64, MTOK / 128), 256, GEMM_SMEM(2)>>>(
        ubuf, w2, fc2_b, x1, (float*)d_out, nullptr,
        DIM, HIDDEN, nullptr, nullptr, nullptr);
}

// round 16
// speedup vs baseline: 1.0432x; 1.0432x over previous
#include <cuda_runtime.h>
#include <cuda_fp16.h>
#include <cstdint>
#include <cstddef>

// ---------------- problem constants ----------------
#define BATCH   4
#define SEQ     2048
#define DIM     768
#define HEADS   12
#define HEAD_D  64
#define HIDDEN  3072
#define MTOK    (BATCH * SEQ)        // 8192 tokens
#define QKV_N   (3 * DIM)            // 2304
#define SCALE_ATT 0.125f             // 64^-0.5
#define LN_EPS  1e-5f

// ---------------- scratch (alloc-free: __device__ globals) ----------------
__device__ float g_x1 [(size_t)MTOK * DIM];       // residual after attn branch

__device__ __align__(16) __half g_qkv[(size_t)MTOK * QKV_N]; // q/k/v fp16
__device__ __align__(16) __half g_h  [(size_t)MTOK * DIM];   // LN out fp16
__device__ __align__(16) __half g_at [(size_t)MTOK * DIM];   // attention out fp16
__device__ __align__(16) __half g_u  [(size_t)MTOK * HIDDEN];// FC1/gelu out fp16

// transposed weights: stored [N, K] fp16
__device__ __align__(16) __half g_wqkv[(size_t)QKV_N * DIM];
__device__ __align__(16) __half g_wprj[(size_t)DIM * DIM];
__device__ __align__(16) __half g_wfc1[(size_t)HIDDEN * DIM];
__device__ __align__(16) __half g_wfc2[(size_t)DIM * HIDDEN];

// =====================================================================
// PTX helpers (sm_80-class: mma.sync / ldmatrix / cp.async — OK on sm_103)
// =====================================================================
__device__ __forceinline__ uint32_t smem_u32(const void* p) {
    uint32_t a;
    asm("{ .reg .u64 t; cvta.to.shared.u64 t, %1; cvt.u32.u64 %0, t; }"
        : "=r"(a) : "l"(p));
    return a;
}

#define LDSM_X4(r, addr)                                                        \
    asm volatile("ldmatrix.sync.aligned.m8n8.x4.shared.b16 {%0,%1,%2,%3}, [%4];"\
        : "=r"((r)[0]), "=r"((r)[1]), "=r"((r)[2]), "=r"((r)[3]) : "r"(addr))

#define LDSM_X4_T(r, addr)                                                      \
    asm volatile("ldmatrix.sync.aligned.m8n8.x4.trans.shared.b16 {%0,%1,%2,%3}, [%4];"\
        : "=r"((r)[0]), "=r"((r)[1]), "=r"((r)[2]), "=r"((r)[3]) : "r"(addr))

#define MMA_F16(d, a, b0, b1)                                                   \
    asm volatile("mma.sync.aligned.m16n8k16.row.col.f32.f16.f16.f32 "           \
        "{%0,%1,%2,%3}, {%4,%5,%6,%7}, {%8,%9}, {%0,%1,%2,%3};"                 \
        : "+f"((d)[0]), "+f"((d)[1]), "+f"((d)[2]), "+f"((d)[3])                \
        : "r"((a)[0]), "r"((a)[1]), "r"((a)[2]), "r"((a)[3]), "r"(b0), "r"(b1))

__device__ __forceinline__ void cp16(uint32_t dst, const void* src) {
    asm volatile("cp.async.cg.shared.global [%0], [%1], 16;"
                 :: "r"(dst), "l"(src) : "memory");
}
#define CP_COMMIT() asm volatile("cp.async.commit_group;" ::: "memory")
#define CP_WAIT1()  asm volatile("cp.async.wait_group 1;" ::: "memory")
#define CP_WAIT0()  asm volatile("cp.async.wait_group 0;" ::: "memory")

__device__ __forceinline__ uint32_t pack_f16(float x, float y) {
    __half2 t = __halves2half2(__float2half_rn(x), __float2half_rn(y));
    return *(uint32_t*)&t;
}

__device__ __forceinline__ void store_h2(__half* p, float a, float b) {
    __half2 t = __halves2half2(__float2half_rn(a), __float2half_rn(b));
    *(__half2*)p = t;
}

// =====================================================================
// Combined weight convert: all four W[K,N] fp32 -> Wt[N,K] fp16
// =====================================================================
#define WCONV_BLOCKS 6912

__global__ __launch_bounds__(256) void wconv_all_kernel(
    const float* __restrict__ qkv_w, __half* __restrict__ wq,
    const float* __restrict__ proj_w, __half* __restrict__ wp,
    const float* __restrict__ fc1_w, __half* __restrict__ w1,
    const float* __restrict__ fc2_w, __half* __restrict__ w2)
{
    int bid = blockIdx.x;
    const float* W; __half* T; int K, N, nx;
    if (bid < 1728)      { W = qkv_w;  T = wq; K = DIM;    N = QKV_N;  nx = 72; }
    else if (bid < 2304) { bid -= 1728; W = proj_w; T = wp; K = DIM;   N = DIM;    nx = 24; }
    else if (bid < 4608) { bid -= 2304; W = fc1_w;  T = w1; K = DIM;   N = HIDDEN; nx = 96; }
    else                 { bid -= 4608; W = fc2_w;  T = w2; K = HIDDEN; N = DIM;   nx = 24; }
    const int n0 = (bid % nx) * 32, k0 = (bid / nx) * 32;

    __shared__ float t[32][33];
    const int tx = threadIdx.x, ty = threadIdx.y;
    #pragma unroll
    for (int j = 0; j < 4; j++)
        t[ty + 8 * j][tx] = W[(size_t)(k0 + ty + 8 * j) * N + n0 + tx];
    __syncthreads();
    #pragma unroll
    for (int j = 0; j < 4; j++)
        T[(size_t)(n0 + ty + 8 * j) * K + k0 + tx] = __float2half_rn(t[tx][ty + 8 * j]);
}

// =====================================================================
// LayerNorm -> fp16
// =====================================================================
__global__ __launch_bounds__(256) void ln_kernel(
    const float* __restrict__ x, const float* __restrict__ gamma,
    const float* __restrict__ beta, __half* __restrict__ out)
{
    const int row = blockIdx.x;
    const int tid = threadIdx.x;
    const float* xr = x + (size_t)row * DIM;

    float v0 = xr[tid], v1 = xr[tid + 256], v2 = xr[tid + 512];
    float s = v0 + v1 + v2;
    float q = v0 * v0 + v1 * v1 + v2 * v2;

    __shared__ float ws[8], wq[8];
    #pragma unroll
    for (int o = 16; o; o >>= 1) {
        s += __shfl_xor_sync(0xffffffffu, s, o);
        q += __shfl_xor_sync(0xffffffffu, q, o);
    }
    if ((tid & 31) == 0) { ws[tid >> 5] = s; wq[tid >> 5] = q; }
    __syncthreads();
    float ts = 0.f, tq = 0.f;
    #pragma unroll
    for (int i = 0; i < 8; i++) { ts += ws[i]; tq += wq[i]; }

    const float mean = ts * (1.0f / DIM);
    const float var  = tq * (1.0f / DIM) - mean * mean;
    const float rstd = rsqrtf(var + LN_EPS);

    const size_t rb = (size_t)row * DIM;
    #pragma unroll
    for (int j = 0; j < 3; j++) {
        const int c = tid + j * 256;
        const float v = (j == 0 ? v0 : (j == 1 ? v1 : v2));
        out[rb + c] = __float2half_rn((v - mean) * rstd * gamma[c] + beta[c]);
    }
}

// =====================================================================
// fp16 tensor-core GEMM via mma.sync.m16n8k16 (unchanged from R14)
// =====================================================================
#define GEMM_SMEM(NJ) (3 * (16384 + 4096 * (NJ)))

template<int MODE, int NJ>
__global__ __launch_bounds__(256, 2) void tc_gemm(
    const __half* __restrict__ A, const __half* __restrict__ B,
    const float* __restrict__ bias, const float* __restrict__ res,
    float* __restrict__ outf, __half* __restrict__ out16,
    int N, int K,
    const float* __restrict__ pga, const float* __restrict__ pgb,
    const float* __restrict__ pgc)
{
    constexpr int BN = 32 * NJ;
    constexpr int STAGE = 16384 + 4096 * NJ;
    extern __shared__ char sm[];
    const uint32_t sbase = smem_u32(sm);
    const int tid = threadIdx.x;
    const int lane = tid & 31, wid = tid >> 5;
    const int wm = wid & 3, wn = wid >> 2;
    const int m0 = blockIdx.y * 128, n0 = blockIdx.x * BN;
    const int nt = K >> 6;

    const __half* agsrc[4]; uint32_t asoff[4];
    #pragma unroll
    for (int i = 0; i < 4; i++) {
        const int id = tid + i * 256;
        const int row = id >> 3, c = id & 7;
        agsrc[i] = A + (size_t)(m0 + row) * K + c * 8;
        asoff[i] = row * 128 + ((c ^ (row & 7)) << 4);
    }
    const __half* bgsrc[NJ]; uint32_t bsoff[NJ];
    #pragma unroll
    for (int i = 0; i < NJ; i++) {
        const int id = tid + i * 256;
        const int row = id >> 3, c = id & 7;
        bgsrc[i] = B + (size_t)(n0 + row) * K + c * 8;
        bsoff[i] = 16384 + row * 128 + ((c ^ (row & 7)) << 4);
    }

    #define LOAD_STAGE(kt, slot) do {                                          \
        const uint32_t sb_ = sbase + (uint32_t)(slot) * STAGE;                  \
        const size_t ko_ = (size_t)(kt) * 64;                                   \
        _Pragma("unroll")                                                       \
        for (int i_ = 0; i_ < 4; i_++)                                          \
            cp16(sb_ + asoff[i_], agsrc[i_] + ko_);                             \
        _Pragma("unroll")                                                       \
        for (int i_ = 0; i_ < NJ; i_++)                                         \
            cp16(sb_ + bsoff[i_], bgsrc[i_] + ko_);                             \
    } while (0)

    LOAD_STAGE(0, 0); CP_COMMIT();
    LOAD_STAGE(1, 1); CP_COMMIT();

    uint32_t a_off[2][4];
    #pragma unroll
    for (int mi = 0; mi < 2; mi++) {
        const int row = wm * 32 + mi * 16 + (lane & 15);
        const int kbit = (lane >> 4) & 1;
        #pragma unroll
        for (int ks = 0; ks < 4; ks++) {
            const int chi = ks * 2 + kbit;
            a_off[mi][ks] = row * 128 + ((chi ^ (row & 7)) << 4);
        }
    }
    uint32_t b_off[NJ][4];
    #pragma unroll
    for (int nj = 0; nj < NJ; nj++) {
        const int nrow = wn * (16 * NJ) + nj * 16 + (lane & 7) + ((lane >> 4) << 3);
        const int kbit = (lane >> 3) & 1;
        #pragma unroll
        for (int ks = 0; ks < 4; ks++) {
            const int chi = ks * 2 + kbit;
            b_off[nj][ks] = 16384 + nrow * 128 + ((chi ^ (nrow & 7)) << 4);
        }
    }

    float acc[2][2 * NJ][4] = {};

    for (int kt = 0; kt < nt; kt++) {
        CP_WAIT1();
        __syncthreads();
        const uint32_t sb = sbase + (uint32_t)(kt % 3) * STAGE;

        #pragma unroll
        for (int ks = 0; ks < 4; ks++) {
            uint32_t ar[2][4];
            LDSM_X4(ar[0], sb + a_off[0][ks]);
            LDSM_X4(ar[1], sb + a_off[1][ks]);
            #pragma unroll
            for (int nj = 0; nj < NJ; nj++) {
                uint32_t br[4];
                LDSM_X4(br, sb + b_off[nj][ks]);
                #pragma unroll
                for (int mi = 0; mi < 2; mi++) {
                    MMA_F16(acc[mi][nj * 2    ], ar[mi], br[0], br[1]);
                    MMA_F16(acc[mi][nj * 2 + 1], ar[mi], br[2], br[3]);
                }
            }
        }
        if (kt + 2 < nt) LOAD_STAGE(kt + 2, (kt + 2) % 3);
        CP_COMMIT();
    }

    float gaV = 0.f, gbV = 0.f, gcV = 0.f;
    if (MODE == 2) { gaV = *pga; gbV = *pgb; gcV = *pgc; }

    #pragma unroll
    for (int mi = 0; mi < 2; mi++) {
        const int ma = m0 + wm * 32 + mi * 16 + (lane >> 2);
        #pragma unroll
        for (int t = 0; t < 2 * NJ; t++) {
            const int n = n0 + wn * (16 * NJ) + t * 8 + ((lane & 3) << 1);
            const float b0 = bias[n], b1 = bias[n + 1];
            #pragma unroll
            for (int half = 0; half < 2; half++) {
                const int m = ma + half * 8;
                float v0 = acc[mi][t][half * 2]     + b0;
                float v1 = acc[mi][t][half * 2 + 1] + b1;
                const size_t idx = (size_t)m * N + n;
                if (MODE == 2) {
                    v0 = fmaf(fmaf(gaV, v0, gbV), v0, gcV);
                    v1 = fmaf(fmaf(gaV, v1, gbV), v1, gcV);
                    store_h2(out16 + idx, v0, v1);
                } else if (MODE == 3) {
                    store_h2(out16 + idx, v0, v1);
                } else {
                    const float2 rv = *(const float2*)(res + idx);
                    *(float2*)(outf + idx) = make_float2(v0 + rv.x, v1 + rv.y);
                }
            }
        }
    }
    #undef LOAD_STAGE
}

// =====================================================================
// Tensor-core fused attention (R14 8-warp layout + triple-buffered K/V,
// single barrier per key-tile — same proof as the GEMM barrier removal):
//   S = QK^T; P = max(pa2*S^2 + pb2*S + pc, 1e-6); O = (P V)/rowsum(P)
// 256 threads (8 warps x 16 queries = 128-query tile), 64-key tiles.
// smem: Q 16KB + 3x(K 8KB + V 8KB) = 64KB dynamic. 2 CTAs/SM.
// =====================================================================
#define ATTN_SMEM_BYTES (16384 + 3 * 2 * 8192)

__global__ __launch_bounds__(256, 2) void attn_tc_kernel(
    const __half* __restrict__ qkv, __half* __restrict__ out,
    const float* __restrict__ pa_, const float* __restrict__ pb_,
    const float* __restrict__ pc_)
{
    extern __shared__ char smA[];
    const uint32_t sQ = smem_u32(smA);
    uint32_t sK[3], sV[3];
    #pragma unroll
    for (int i = 0; i < 3; i++) {
        sK[i] = sQ + 16384 + i * 16384;
        sV[i] = sK[i] + 8192;
    }

    const int tid = threadIdx.x, lane = tid & 31, warp = tid >> 5;
    const int bh = blockIdx.y, b = bh / HEADS, h = bh % HEADS;
    const int q0 = blockIdx.x * 128;
    const size_t tok0 = (size_t)b * SEQ;

    const float pa2 = *pa_ * (SCALE_ATT * SCALE_ATT);
    const float pb2 = *pb_ * SCALE_ATT;
    const float pc  = *pc_;

    // Q loads: 128 rows x 8 chunks = 1024 chunks / 256 thr = 4 each
    const int qrow = tid >> 1;
    const int qc0  = (tid & 1) * 4;
    const __half* qsrc = qkv + (tok0 + q0 + qrow) * QKV_N + h * HEAD_D + qc0 * 8;
    #pragma unroll
    for (int j = 0; j < 4; j++)
        cp16(sQ + qrow * 128 + (((qc0 + j) ^ (qrow & 7)) << 4), qsrc + j * 8);

    // K/V loads: 64 rows x 8 chunks = 512 chunks / 256 thr = 2 each
    const int krow = tid >> 2;
    const int kc0  = (tid & 3) * 2;
    const __half* ksrc = qkv + (tok0 + krow) * QKV_N + DIM + h * HEAD_D + kc0 * 8;
    const __half* vsrc = ksrc + DIM;
    uint32_t kvoff[2];
    #pragma unroll
    for (int j = 0; j < 2; j++)
        kvoff[j] = krow * 128 + (((kc0 + j) ^ (krow & 7)) << 4);

    #define ATTN_LOAD(t_, slot_) do {                                          \
        const size_t roff_ = (size_t)(t_) * 64 * QKV_N;                         \
        _Pragma("unroll")                                                       \
        for (int j_ = 0; j_ < 2; j_++) {                                        \
            cp16(sK[slot_] + kvoff[j_], ksrc + roff_ + j_ * 8);                 \
            cp16(sV[slot_] + kvoff[j_], vsrc + roff_ + j_ * 8);                 \
        }                                                                       \
    } while (0)

    // preload tiles 0 and 1 (Q rides with tile 0's group)
    ATTN_LOAD(0, 0); CP_COMMIT();
    ATTN_LOAD(1, 1); CP_COMMIT();

    const int g = lane >> 3, r = lane & 7;
    const int rowadd = (g & 1) * 8 + r;
    const int cadd = g >> 1;

    float acc_o[8][4] = {};
    float rsum[2] = {};
    const int NT = SEQ / 64;

    uint32_t qreg[4][4];
    bool qloaded = false;

    for (int t = 0; t < NT; t++) {
        CP_WAIT1();
        __syncthreads();

        if (!qloaded) {   // Q arrived with tile 0's group
            const uint32_t qb = sQ + (warp * 16 + rowadd) * 128;
            #pragma unroll
            for (int s = 0; s < 4; s++)
                LDSM_X4(qreg[s], qb + (((2 * s + cadd) ^ r) << 4));
            qloaded = true;
        }

        const uint32_t sk = sK[t % 3], sv = sV[t % 3];

        // ---- S = Q K^T ----
        float acc_s[8][4] = {};
        #pragma unroll
        for (int s = 0; s < 4; s++) {
            const uint32_t coff = ((2 * s + cadd) ^ r) << 4;
            #pragma unroll
            for (int p = 0; p < 4; p++) {
                uint32_t kb[4];
                LDSM_X4(kb, sk + (16 * p + rowadd) * 128 + coff);
                MMA_F16(acc_s[2 * p    ], qreg[s], kb[0], kb[2]);
                MMA_F16(acc_s[2 * p + 1], qreg[s], kb[1], kb[3]);
            }
        }

        // ---- poly activation + clamp + rowsum ----
        #pragma unroll
        for (int j = 0; j < 8; j++)
            #pragma unroll
            for (int e = 0; e < 4; e++) {
                const float sv_ = acc_s[j][e];
                float pv = fmaf(fmaf(pa2, sv_, pb2), sv_, pc);
                pv = fmaxf(pv, 1e-6f);
                acc_s[j][e] = pv;
                rsum[e >> 1] += pv;
            }

        // ---- O += P V ----
        #pragma unroll
        for (int s = 0; s < 4; s++) {
            uint32_t pf[4];
            pf[0] = pack_f16(acc_s[2 * s][0],     acc_s[2 * s][1]);
            pf[1] = pack_f16(acc_s[2 * s][2],     acc_s[2 * s][3]);
            pf[2] = pack_f16(acc_s[2 * s + 1][0], acc_s[2 * s + 1][1]);
            pf[3] = pack_f16(acc_s[2 * s + 1][2], acc_s[2 * s + 1][3]);
            const uint32_t vrb = sv + (16 * s + rowadd) * 128;
            #pragma unroll
            for (int p = 0; p < 4; p++) {
                uint32_t vb[4];
                LDSM_X4_T(vb, vrb + (((2 * p + cadd) ^ r) << 4));
                MMA_F16(acc_o[2 * p    ], pf, vb[0], vb[1]);
                MMA_F16(acc_o[2 * p + 1], pf, vb[2], vb[3]);
            }
        }

        // no tail barrier: slot (t+2)%3 was last read at iteration t-1,
        // sealed by this iteration's top barrier (GEMM-proven pattern).
        if (t + 2 < NT) ATTN_LOAD(t + 2, (t + 2) % 3);
        CP_COMMIT();
    }
    #undef ATTN_LOAD

    #pragma unroll
    for (int off = 1; off < 4; off <<= 1) {
        rsum[0] += __shfl_xor_sync(0xffffffffu, rsum[0], off);
        rsum[1] += __shfl_xor_sync(0xffffffffu, rsum[1], off);
    }
    const float inv0 = 1.0f / (rsum[0] + 1e-8f);
    const float inv1 = 1.0f / (rsum[1] + 1e-8f);

    const int row0 = q0 + warp * 16 + (lane >> 2);
    const int dcol = h * HEAD_D + 2 * (lane & 3);
    #pragma unroll
    for (int j = 0; j < 8; j++) {
        const size_t i0 = (tok0 + row0) * DIM + dcol + 8 * j;
        const size_t i1 = (tok0 + row0 + 8) * DIM + dcol + 8 * j;
        store_h2(out + i0, acc_o[j][0] * inv0, acc_o[j][1] * inv0);
        store_h2(out + i1, acc_o[j][2] * inv1, acc_o[j][3] * inv1);
    }
}

// =====================================================================
// Launch
// =====================================================================
extern "C" void kernel_launch(void* const* d_in, const int* in_sizes, int n_in,
                              void* d_out, int out_size)
{
    const float* x      = (const float*)d_in[0];
    const float* ln1_g  = (const float*)d_in[1];
    const float* ln1_b  = (const float*)d_in[2];
    const float* ln2_g  = (const float*)d_in[3];
    const float* ln2_b  = (const float*)d_in[4];
    const float* qkv_w  = (const float*)d_in[5];
    const float* qkv_b  = (const float*)d_in[6];
    const float* proj_w = (const float*)d_in[7];
    const float* proj_b = (const float*)d_in[8];
    const float* fc1_w  = (const float*)d_in[9];
    const float* fc1_b  = (const float*)d_in[10];
    const float* fc2_w  = (const float*)d_in[11];
    const float* fc2_b  = (const float*)d_in[12];
    const float* attn_a = (const float*)d_in[13];
    const float* attn_b = (const float*)d_in[14];
    const float* attn_c = (const float*)d_in[15];
    const float* gelu_a = (const float*)d_in[16];
    const float* gelu_b = (const float*)d_in[17];
    const float* gelu_c = (const float*)d_in[18];

    float *x1;
    __half *qkvh, *hbuf, *atbuf, *ubuf, *wq, *wp, *w1, *w2;
    cudaGetSymbolAddress((void**)&x1,    g_x1);
    cudaGetSymbolAddress((void**)&qkvh,  g_qkv);
    cudaGetSymbolAddress((void**)&hbuf,  g_h);
    cudaGetSymbolAddress((void**)&atbuf, g_at);
    cudaGetSymbolAddress((void**)&ubuf,  g_u);
    cudaGetSymbolAddress((void**)&wq,    g_wqkv);
    cudaGetSymbolAddress((void**)&wp,    g_wprj);
    cudaGetSymbolAddress((void**)&w1,    g_wfc1);
    cudaGetSymbolAddress((void**)&w2,    g_wfc2);

    cudaFuncSetAttribute(tc_gemm<1, 2>, cudaFuncAttributeMaxDynamicSharedMemorySize,
                         GEMM_SMEM(2));
    cudaFuncSetAttribute(tc_gemm<2, 4>, cudaFuncAttributeMaxDynamicSharedMemorySize,
                         GEMM_SMEM(4));
    cudaFuncSetAttribute(tc_gemm<3, 4>, cudaFuncAttributeMaxDynamicSharedMemorySize,
                         GEMM_SMEM(4));
    cudaFuncSetAttribute(attn_tc_kernel, cudaFuncAttributeMaxDynamicSharedMemorySize,
                         ATTN_SMEM_BYTES);

    // 0) all weight transposes + fp16 conversion in ONE launch
    wconv_all_kernel<<<WCONV_BLOCKS, dim3(32, 8)>>>(
        qkv_w, wq, proj_w, wp, fc1_w, w1, fc2_w, w2);

    // 1) LN1 -> fp16
    ln_kernel<<<MTOK, 256>>>(x, ln1_g, ln1_b, hbuf);

    // 2) QKV GEMM -> fp16 q/k/v   (128x128 tiles)
    tc_gemm<3, 4><<<dim3(QKV_N / 128, MTOK / 128), 256, GEMM_SMEM(4)>>>(
        hbuf, wq, qkv_b, nullptr, nullptr, qkvh,
        QKV_N, DIM, nullptr, nullptr, nullptr);

    // 3) tensor-core attention (128-query tiles, triple-buffered K/V)
    attn_tc_kernel<<<dim3(SEQ / 128, BATCH * HEADS), 256, ATTN_SMEM_BYTES>>>(
        qkvh, atbuf, attn_a, attn_b, attn_c);

    // 4) proj GEMM + residual(x) -> x1 (fp32)   (128x64 tiles)
    tc_gemm<1, 2><<<dim3(DIM / 64, MTOK / 128), 256, GEMM_SMEM(2)>>>(
        atbuf, wp, proj_b, x, x1, nullptr,
        DIM, DIM, nullptr, nullptr, nullptr);

    // 5) LN2 -> fp16
    ln_kernel<<<MTOK, 256>>>(x1, ln2_g, ln2_b, hbuf);

    // 6) FC1 + poly-GELU -> u fp16   (128x128 tiles)
    tc_gemm<2, 4><<<dim3(HIDDEN / 128, MTOK / 128), 256, GEMM_SMEM(4)>>>(
        hbuf, w1, fc1_b, nullptr, nullptr, ubuf,
        HIDDEN, DIM, gelu_a, gelu_b, gelu_c);

    // 7) FC2 + residual(x1) -> out (fp32)   (128x64 tiles)
    tc_gemm<1, 2><<<dim3(DIM / 64, MTOK / 128), 256, GEMM_SMEM(2)>>>(
        ubuf, w2, fc2_b, x1, (float*)d_out, nullptr,
        DIM, HIDDEN, nullptr, nullptr, nullptr);
}